// round 12
// baseline (speedup 1.0000x reference)
#include <cuda_runtime.h>

// out[b, i, f] = x[b, i] * W[i, f] + bias[i, f]
// BS=16384, DEMO_DIM=32, FEAT_DIM=256 -> 512 MiB fp32 out. Pure HBM-store-bound.
//
// Round-11: single-variable ablation of the __stcs hint (never tested in
// isolation). Everything else identical to the R3/R10 plateau kernel
// (74.2-75.3us, DRAM ~80%, occ ~92%, regs 32).
//
// Rationale: .cs (evict-first) may drain L2 lines before both 64B sectors
// of a 128B line have landed, producing partial-line DRAM writes. Default
// policy lets full lines coalesce in L2 before drain; the hot read set
// (64 KiB W/b + 2 MiB x) is tiny and stays resident either way.
//
//  - BPT=8 batches per thread, fixed (i, f4): W/b in registers, 8x reuse.
//  - 16384 CTAs x 256 threads, 32 regs -> occ ~93%.
//  - Plain coalesced float4 stores (this round's one change).

#define BS        16384
#define DEMO_DIM  32
#define FEAT_DIM  256
#define F4        (FEAT_DIM / 4)                 // 64 float4 per (b,i)
#define ROW4      (DEMO_DIM * F4)                // 2048 float4 per batch
#define BPT       8                              // batches per thread
#define THREADS   256
#define OFF_CHUNKS (ROW4 / THREADS)              // 8 chunks of 256 float4 per row
#define NBLOCKS   ((BS / BPT) * OFF_CHUNKS)      // 2048 * 8 = 16384 blocks

__global__ __launch_bounds__(THREADS) void demo_proj_kernel(
    const float*  __restrict__ x,     // [BS, DEMO_DIM]
    const float4* __restrict__ W4,    // [DEMO_DIM, F4]
    const float4* __restrict__ B4,    // [DEMO_DIM, F4]
    float4*       __restrict__ out4)  // [BS, DEMO_DIM, F4]
{
    // Low 3 bits of blockIdx pick the 256-float4 chunk within the
    // 2048-float4 row; high bits pick the group of BPT batches.
    unsigned off_chunk = blockIdx.x & (OFF_CHUNKS - 1);
    unsigned bgroup    = blockIdx.x >> 3;

    unsigned off = off_chunk * THREADS + threadIdx.x;   // 0..2047, fixed
    unsigned i   = off >> 6;                            // demo index, fixed
    unsigned f4  = off & (F4 - 1);                      // feature chunk, fixed

    // Per-thread W/b loaded ONCE; reused for all BPT batches.
    float4 w  = __ldg(&W4[i * F4 + f4]);
    float4 bv = __ldg(&B4[i * F4 + f4]);

    unsigned bb0 = bgroup * BPT;
    const float* xrow = x + bb0 * DEMO_DIM + i;
    float4* dst = out4 + (size_t)bb0 * ROW4 + off;

#pragma unroll
    for (int k = 0; k < BPT; k++) {
        float xv = __ldg(xrow + k * DEMO_DIM);   // uniform per warp, L1 hit
        float4 o;
        o.x = fmaf(xv, w.x, bv.x);
        o.y = fmaf(xv, w.y, bv.y);
        o.z = fmaf(xv, w.z, bv.z);
        o.w = fmaf(xv, w.w, bv.w);
        dst[(size_t)k * ROW4] = o;               // plain coalesced STG.128
    }
}

extern "C" void kernel_launch(void* const* d_in, const int* in_sizes, int n_in,
                              void* d_out, int out_size)
{
    const float*  x  = (const float*)d_in[0];
    const float4* W4 = (const float4*)d_in[1];
    const float4* B4 = (const float4*)d_in[2];
    float4* out4 = (float4*)d_out;

    demo_proj_kernel<<<NBLOCKS, THREADS>>>(x, W4, B4, out4);
}

// round 14
// speedup vs baseline: 1.0492x; 1.0492x over previous
#include <cuda_runtime.h>

// out[b, i, f] = x[b, i] * W[i, f] + bias[i, f]
// BS=16384, DEMO_DIM=32, FEAT_DIM=256 -> 512 MiB fp32 out. Pure HBM-store-bound.
//
// FINAL (round-12): exact revert to the round-3 record configuration
// (74.2us, DRAM=80.4%, occ=92.7%). Ablation history:
//   - BPT=16 / grid 8192:  75.7us (occ 69% — occupancy is load-bearing)
//   - plain STG vs __stcs: 77.9us (.cs evict-first is worth ~3%)
//   - DRAM pinned at 79-80% (6.3 TB/s) across all variants = HBM write
//     drain ceiling; no SM-side lever remains (issue 13%, pipes idle).
//
//  - BPT=8 batches per thread, fixed (i, f4): W/b in registers, 8x reuse.
//  - 16384 CTAs x 256 threads, 32 regs -> occ ~93%, ~14 waves.
//  - __stcs streaming stores, warp-coalesced 512B per warp-store.
//  - Interleaved load->fma->store (scoreboard overlaps next x load with
//    the current store).

#define BS        16384
#define DEMO_DIM  32
#define FEAT_DIM  256
#define F4        (FEAT_DIM / 4)                 // 64 float4 per (b,i)
#define ROW4      (DEMO_DIM * F4)                // 2048 float4 per batch
#define BPT       8                              // batches per thread
#define THREADS   256
#define OFF_CHUNKS (ROW4 / THREADS)              // 8 chunks of 256 float4 per row
#define NBLOCKS   ((BS / BPT) * OFF_CHUNKS)      // 2048 * 8 = 16384 blocks

__global__ __launch_bounds__(THREADS) void demo_proj_kernel(
    const float*  __restrict__ x,     // [BS, DEMO_DIM]
    const float4* __restrict__ W4,    // [DEMO_DIM, F4]
    const float4* __restrict__ B4,    // [DEMO_DIM, F4]
    float4*       __restrict__ out4)  // [BS, DEMO_DIM, F4]
{
    // Low 3 bits of blockIdx pick the 256-float4 chunk within the
    // 2048-float4 row; high bits pick the group of BPT batches.
    int off_chunk = blockIdx.x & (OFF_CHUNKS - 1);
    int bgroup    = blockIdx.x >> 3;

    int off = off_chunk * THREADS + threadIdx.x;   // 0..2047, fixed per thread
    int i   = off >> 6;                            // demo index, fixed
    int f4  = off & (F4 - 1);                      // feature chunk, fixed

    // Per-thread W/b loaded ONCE; reused for all BPT batches.
    float4 w  = __ldg(&W4[i * F4 + f4]);
    float4 bv = __ldg(&B4[i * F4 + f4]);

    int bb0 = bgroup * BPT;
    const float* xrow = x + bb0 * DEMO_DIM + i;
    float4* dst = out4 + (long long)bb0 * ROW4 + off;

#pragma unroll
    for (int k = 0; k < BPT; k++) {
        float xv = __ldg(xrow + k * DEMO_DIM);     // uniform per warp, L1 hit
        float4 o;
        o.x = fmaf(xv, w.x, bv.x);
        o.y = fmaf(xv, w.y, bv.y);
        o.z = fmaf(xv, w.z, bv.z);
        o.w = fmaf(xv, w.w, bv.w);
        __stcs(dst + (long long)k * ROW4, o);      // streaming store, coalesced
    }
}

extern "C" void kernel_launch(void* const* d_in, const int* in_sizes, int n_in,
                              void* d_out, int out_size)
{
    const float*  x  = (const float*)d_in[0];
    const float4* W4 = (const float4*)d_in[1];
    const float4* B4 = (const float4*)d_in[2];
    float4* out4 = (float4*)d_out;

    demo_proj_kernel<<<NBLOCKS, THREADS>>>(x, W4, B4, out4);
}